// round 2
// baseline (speedup 1.0000x reference)
#include <cuda_runtime.h>

#define V_SIZE 128000
#define R_MAX 512
#define PEN_LAMBDA 0.5f

// Scratch (no allocations allowed in kernel_launch)
__device__ float g_pen[V_SIZE];
__device__ float g_gates[R_MAX];
__device__ float g_firing[R_MAX];

// ---------------------------------------------------------------------------
// k_init: zero pen_1d + firing, compute gates = sigmoid(gate_logits)
// ---------------------------------------------------------------------------
__global__ void k_init(const float* __restrict__ gate_logits, int R) {
    int i = blockIdx.x * blockDim.x + threadIdx.x;
    int stride = gridDim.x * blockDim.x;
    for (int j = i; j < V_SIZE; j += stride) g_pen[j] = 0.0f;
    if (i < R) {
        float x = gate_logits[i];
        g_gates[i] = 1.0f / (1.0f + __expf(-x));
        g_firing[i] = 0.0f;
    }
}

// ---------------------------------------------------------------------------
// k_scatter: pen[token] += gates[rule]*lambda ; firing[rule] = 1
// E divisible by 4 (E = 1e6); vectorized id loads.
// ---------------------------------------------------------------------------
__global__ void k_scatter(const int* __restrict__ rule_ids,
                          const int* __restrict__ token_ids, int E) {
    int i4 = (blockIdx.x * blockDim.x + threadIdx.x) * 4;
    if (i4 + 3 < E) {
        int4 r = *reinterpret_cast<const int4*>(rule_ids + i4);
        int4 t = *reinterpret_cast<const int4*>(token_ids + i4);
        atomicAdd(&g_pen[t.x], g_gates[r.x] * PEN_LAMBDA);
        atomicAdd(&g_pen[t.y], g_gates[r.y] * PEN_LAMBDA);
        atomicAdd(&g_pen[t.z], g_gates[r.z] * PEN_LAMBDA);
        atomicAdd(&g_pen[t.w], g_gates[r.w] * PEN_LAMBDA);
        // plain stores: idempotent (all write 1.0f)
        g_firing[r.x] = 1.0f;
        g_firing[r.y] = 1.0f;
        g_firing[r.z] = 1.0f;
        g_firing[r.w] = 1.0f;
    } else {
        for (int i = i4; i < E; i++) {
            int r = rule_ids[i], t = token_ids[i];
            atomicAdd(&g_pen[t], g_gates[r] * PEN_LAMBDA);
            g_firing[r] = 1.0f;
        }
    }
}

// ---------------------------------------------------------------------------
// k_loss: coverage_loss = -(gates*firing).sum() / max(firing.sum(), 1)
// One block of 512 threads.
// ---------------------------------------------------------------------------
__global__ void k_loss(float* __restrict__ out_loss, int R) {
    __shared__ float sg[16], sf[16];
    int tid = threadIdx.x;
    float f = (tid < R) ? g_firing[tid] : 0.0f;
    float gf = (tid < R) ? g_gates[tid] * f : 0.0f;
    // warp reduce
    #pragma unroll
    for (int off = 16; off > 0; off >>= 1) {
        gf += __shfl_down_sync(0xFFFFFFFF, gf, off);
        f  += __shfl_down_sync(0xFFFFFFFF, f,  off);
    }
    int warp = tid >> 5;
    if ((tid & 31) == 0) { sg[warp] = gf; sf[warp] = f; }
    __syncthreads();
    if (warp == 0) {
        int nw = blockDim.x >> 5;
        float g2 = (tid < nw) ? sg[tid] : 0.0f;
        float f2 = (tid < nw) ? sf[tid] : 0.0f;
        #pragma unroll
        for (int off = 8; off > 0; off >>= 1) {
            g2 += __shfl_down_sync(0xFFFF, g2, off);
            f2 += __shfl_down_sync(0xFFFF, f2, off);
        }
        if (tid == 0) out_loss[0] = -g2 / fmaxf(f2, 1.0f);
    }
}

// ---------------------------------------------------------------------------
// k_bcast: modified[i] = logits[i] - pen[i % V]; penalties[i] = pen[i % V]
// logits/modified are 16B aligned -> float4. penalties starts at a +1 float
// offset (only 4B aligned) -> scalar stores there.
// ---------------------------------------------------------------------------
__global__ void k_bcast(const float* __restrict__ logits,
                        float* __restrict__ modified,
                        float* __restrict__ penalties,  // 4B-aligned only
                        int BV4) {
    const int V4 = V_SIZE / 4;
    int i = blockIdx.x * blockDim.x + threadIdx.x;
    if (i < BV4) {
        float4 l = reinterpret_cast<const float4*>(logits)[i];
        int v4 = i % V4;
        float4 p = reinterpret_cast<const float4*>(g_pen)[v4];
        float4 m;
        m.x = l.x - p.x; m.y = l.y - p.y; m.z = l.z - p.z; m.w = l.w - p.w;
        reinterpret_cast<float4*>(modified)[i] = m;
        float* pd = penalties + 4 * (size_t)i;
        pd[0] = p.x; pd[1] = p.y; pd[2] = p.z; pd[3] = p.w;
    }
}

extern "C" void kernel_launch(void* const* d_in, const int* in_sizes, int n_in,
                              void* d_out, int out_size) {
    const float* logits      = (const float*)d_in[0];
    const float* gate_logits = (const float*)d_in[1];
    const int*   rule_ids    = (const int*)d_in[2];
    const int*   token_ids   = (const int*)d_in[3];

    int BV = in_sizes[0];       // 64 * 128000 = 8192000
    int R  = in_sizes[1];       // 512
    int E  = in_sizes[2];       // 1e6

    float* out       = (float*)d_out;
    float* modified  = out;                 // [BV]
    float* out_loss  = out + BV;            // [1]
    float* penalties = out + BV + 1;        // [BV], 4B aligned

    // 1) init (zero pen + firing, compute gates)
    {
        int threads = 256;
        int blocks = (V_SIZE + threads - 1) / threads;   // 500
        k_init<<<blocks, threads>>>(gate_logits, R);
    }
    // 2) scatter
    {
        int threads = 256;
        int n4 = (E + 3) / 4;
        int blocks = (n4 + threads - 1) / threads;
        k_scatter<<<blocks, threads>>>(rule_ids, token_ids, E);
    }
    // 3) coverage loss
    k_loss<<<1, 512>>>(out_loss, R);
    // 4) broadcast modified + penalties
    {
        int BV4 = BV / 4;
        int threads = 256;
        int blocks = (BV4 + threads - 1) / threads;
        k_bcast<<<blocks, threads>>>(logits, modified, penalties, BV4);
    }
}

// round 4
// speedup vs baseline: 4.2515x; 4.2515x over previous
#include <cuda_runtime.h>

#define V_SIZE 128000
#define V4_SIZE 32000          // V_SIZE/4
#define R_MAX 512
#define PEN_LAMBDA 0.5f

// Scratch (__device__ globals; no allocations allowed)
__device__ float g_pen[V_SIZE];
__device__ float g_pshift[V_SIZE];   // g_pshift[v] = g_pen[(v+3)%V]
__device__ float g_firing[R_MAX];

// ---------------------------------------------------------------------------
// k_zero: zero pen + firing. 125 blocks x 256 = 32000 threads, 1 float4 each.
// ---------------------------------------------------------------------------
__global__ void k_zero() {
    int i = blockIdx.x * blockDim.x + threadIdx.x;
    reinterpret_cast<float4*>(g_pen)[i] = make_float4(0.f, 0.f, 0.f, 0.f);
    if (i < R_MAX / 4)
        reinterpret_cast<float4*>(g_firing)[i] = make_float4(0.f, 0.f, 0.f, 0.f);
}

// ---------------------------------------------------------------------------
// k_scatter: pen[token] += sigmoid(gate_logit[rule]) * lambda
// 512 threads/CTA, 8 pairs/thread (2x int4). Gates (with lambda folded) and
// firing flags live in smem; firing flushed once per CTA (<=512 stores/CTA
// instead of 1 store per pair).
// ---------------------------------------------------------------------------
__global__ void __launch_bounds__(512) k_scatter(
    const float* __restrict__ gate_logits,
    const int* __restrict__ rule_ids,
    const int* __restrict__ token_ids,
    int n_quads)   // E/4
{
    __shared__ float s_gates[R_MAX];
    __shared__ int   s_fire[R_MAX];
    int tid = threadIdx.x;
    // one gate per thread (blockDim == R_MAX == 512)
    float gl = gate_logits[tid];
    s_gates[tid] = PEN_LAMBDA / (1.0f + __expf(-gl));
    s_fire[tid] = 0;
    __syncthreads();

    #pragma unroll
    for (int p = 0; p < 2; p++) {
        int q = blockIdx.x * 1024 + p * 512 + tid;
        if (q < n_quads) {
            int4 r = reinterpret_cast<const int4*>(rule_ids)[q];
            int4 t = reinterpret_cast<const int4*>(token_ids)[q];
            atomicAdd(&g_pen[t.x], s_gates[r.x]);
            atomicAdd(&g_pen[t.y], s_gates[r.y]);
            atomicAdd(&g_pen[t.z], s_gates[r.z]);
            atomicAdd(&g_pen[t.w], s_gates[r.w]);
            s_fire[r.x] = 1;
            s_fire[r.y] = 1;
            s_fire[r.z] = 1;
            s_fire[r.w] = 1;
        }
    }
    __syncthreads();
    if (s_fire[tid]) g_firing[tid] = 1.0f;   // idempotent across CTAs
}

// ---------------------------------------------------------------------------
// k_post: block 0 computes coverage loss; all blocks build g_pshift
// (the +3-shifted pen copy that makes penalty stores 16B-alignable).
// grid = 64 blocks x 512 threads.
// ---------------------------------------------------------------------------
__global__ void __launch_bounds__(512) k_post(
    const float* __restrict__ gate_logits,
    float* __restrict__ out_loss)
{
    int tid = threadIdx.x;

    if (blockIdx.x == 0) {
        __shared__ float sg[16], sf[16];
        float f = g_firing[tid];
        float g = 1.0f / (1.0f + __expf(-gate_logits[tid]));
        float gf = g * f;
        #pragma unroll
        for (int off = 16; off > 0; off >>= 1) {
            gf += __shfl_down_sync(0xFFFFFFFF, gf, off);
            f  += __shfl_down_sync(0xFFFFFFFF, f,  off);
        }
        int warp = tid >> 5;
        if ((tid & 31) == 0) { sg[warp] = gf; sf[warp] = f; }
        __syncthreads();
        if (warp == 0) {
            float g2 = (tid < 16) ? sg[tid] : 0.0f;
            float f2 = (tid < 16) ? sf[tid] : 0.0f;
            #pragma unroll
            for (int off = 8; off > 0; off >>= 1) {
                g2 += __shfl_down_sync(0xFFFFFFFF, g2, off);
                f2 += __shfl_down_sync(0xFFFFFFFF, f2, off);
            }
            if (tid == 0) out_loss[0] = -g2 / fmaxf(f2, 1.0f);
        }
    }

    // shifted copy: pshift[v] = pen[(v+3)%V]
    int stride = gridDim.x * blockDim.x;       // 32768
    for (int v = blockIdx.x * blockDim.x + tid; v < V_SIZE; v += stride) {
        int src = v + 3;
        if (src >= V_SIZE) src -= V_SIZE;
        g_pshift[v] = g_pen[src];
    }
}

// ---------------------------------------------------------------------------
// k_bcast: modified[i] = logits[i] - pen[i%V]  (aligned float4)
//          penalties[e] = pen[e%V]             (aligned float4 via pshift)
// penalties base is out+BV+1 (4B-aligned); penalties+3 is 16B-aligned, and
// pshift4[m] == pen[(4m+3)%V .. (4m+6)%V] supplies exactly the shifted quads.
// Streaming (__stcs) stores keep logits L2-resident across replays.
// ---------------------------------------------------------------------------
__global__ void k_bcast(const float* __restrict__ logits,
                        float* __restrict__ modified,
                        float* __restrict__ penalties,   // = out + BV + 1
                        int BV4, int pen_quads)
{
    int i = blockIdx.x * blockDim.x + threadIdx.x;
    if (i >= BV4) return;
    int m = i % V4_SIZE;

    float4 l = __ldg(reinterpret_cast<const float4*>(logits) + i);
    float4 p = reinterpret_cast<const float4*>(g_pen)[m];
    float4 o;
    o.x = l.x - p.x; o.y = l.y - p.y; o.z = l.z - p.z; o.w = l.w - p.w;
    __stcs(reinterpret_cast<float4*>(modified) + i, o);

    if (i < pen_quads) {
        float4 ps = reinterpret_cast<const float4*>(g_pshift)[m];
        __stcs(reinterpret_cast<float4*>(penalties + 3) + i, ps);
    }
    if (i == 0) {
        // tail scalars not covered by the aligned window
        penalties[0] = g_pen[0];
        penalties[1] = g_pen[1];
        penalties[2] = g_pen[2];
        // last element: e = BV-1, v = (BV-1)%V = V-1  (BV is a multiple of V)
        int BV = BV4 * 4;
        penalties[BV - 1] = g_pen[V_SIZE - 1];
    }
}

extern "C" void kernel_launch(void* const* d_in, const int* in_sizes, int n_in,
                              void* d_out, int out_size) {
    const float* logits      = (const float*)d_in[0];
    const float* gate_logits = (const float*)d_in[1];
    const int*   rule_ids    = (const int*)d_in[2];
    const int*   token_ids   = (const int*)d_in[3];

    int BV = in_sizes[0];       // 8,192,000
    int E  = in_sizes[2];       // 1,000,000

    float* out       = (float*)d_out;
    float* modified  = out;                 // [BV]
    float* out_loss  = out + BV;            // [1]
    float* penalties = out + BV + 1;        // [BV], 4B-aligned

    // 1) zero scratch
    k_zero<<<125, 256>>>();

    // 2) scatter (8 pairs/thread, 512 threads)
    {
        int n_quads = E / 4;                        // 250,000 (E % 4 == 0)
        int blocks = (n_quads + 1023) / 1024;       // 245
        k_scatter<<<blocks, 512>>>(gate_logits, rule_ids, token_ids, n_quads);
    }

    // 3) loss + shifted pen copy
    k_post<<<64, 512>>>(gate_logits, out_loss);

    // 4) broadcast
    {
        int BV4 = BV / 4;                           // 2,048,000
        int pen_quads = (BV - 3) / 4;               // 2,047,999
        int threads = 256;
        int blocks = (BV4 + threads - 1) / threads;
        k_bcast<<<blocks, threads>>>(logits, modified, penalties, BV4, pen_quads);
    }
}

// round 5
// speedup vs baseline: 4.5990x; 1.0817x over previous
#include <cuda_runtime.h>

#define V_SIZE 128000
#define V4_SIZE 32000          // V_SIZE/4
#define R_MAX 512
#define PEN_LAMBDA 0.5f
#define ROWS_PER_BLK 8         // batch rows per bcast block (64/8 = grid.y)

// Scratch (__device__ globals; no allocations allowed)
__device__ float g_pen[V_SIZE];
__device__ float g_firing[R_MAX];

// ---------------------------------------------------------------------------
// k_zero: zero pen + firing. 125 blocks x 256 threads, 1 float4 each.
// ---------------------------------------------------------------------------
__global__ void k_zero() {
    int i = blockIdx.x * blockDim.x + threadIdx.x;
    reinterpret_cast<float4*>(g_pen)[i] = make_float4(0.f, 0.f, 0.f, 0.f);
    if (i < R_MAX / 4)
        reinterpret_cast<float4*>(g_firing)[i] = make_float4(0.f, 0.f, 0.f, 0.f);
}

// ---------------------------------------------------------------------------
// k_scatter: pen[token] += sigmoid(gate_logit[rule]) * lambda
// 512 threads/CTA, 8 pairs/thread (2x int4). Gates (lambda folded) and firing
// flags in smem; firing flushed once per CTA.
// ---------------------------------------------------------------------------
__global__ void __launch_bounds__(512) k_scatter(
    const float* __restrict__ gate_logits,
    const int* __restrict__ rule_ids,
    const int* __restrict__ token_ids,
    int n_quads)   // E/4
{
    __shared__ float s_gates[R_MAX];
    __shared__ int   s_fire[R_MAX];
    int tid = threadIdx.x;
    float gl = gate_logits[tid];
    s_gates[tid] = PEN_LAMBDA / (1.0f + __expf(-gl));
    s_fire[tid] = 0;
    __syncthreads();

    #pragma unroll
    for (int p = 0; p < 2; p++) {
        int q = blockIdx.x * 1024 + p * 512 + tid;
        if (q < n_quads) {
            int4 r = reinterpret_cast<const int4*>(rule_ids)[q];
            int4 t = reinterpret_cast<const int4*>(token_ids)[q];
            atomicAdd(&g_pen[t.x], s_gates[r.x]);
            atomicAdd(&g_pen[t.y], s_gates[r.y]);
            atomicAdd(&g_pen[t.z], s_gates[r.z]);
            atomicAdd(&g_pen[t.w], s_gates[r.w]);
            s_fire[r.x] = 1;
            s_fire[r.y] = 1;
            s_fire[r.z] = 1;
            s_fire[r.w] = 1;
        }
    }
    __syncthreads();
    if (s_fire[tid]) g_firing[tid] = 1.0f;   // idempotent across CTAs
}

// ---------------------------------------------------------------------------
// k_bcast: fused broadcast + penalties + coverage loss.
// Grid (125, 8), 256 threads. Block (bx, by) covers v-quads
// m in [bx*256, bx*256+256) for batch rows b in [by*8, by*8+8).
// The pen window [4*m0, 4*m0+1028) is staged in smem once; the unaligned
// (+3-shifted) penalty quad is composed from two adjacent smem quads.
// Block (0,0) additionally computes the coverage loss.
// ---------------------------------------------------------------------------
__global__ void __launch_bounds__(256) k_bcast(
    const float* __restrict__ logits,
    const float* __restrict__ gate_logits,
    float* __restrict__ modified,
    float* __restrict__ penalties,   // = out + BV + 1 (4B-aligned)
    float* __restrict__ out_loss,
    int pen_quads)                   // (BV-3)/4
{
    __shared__ float s_pen[1028];
    int tid = threadIdx.x;
    int m0 = blockIdx.x * 256;

    // stage pen window (wrap only possible in the 4-float tail, last block)
    reinterpret_cast<float4*>(s_pen)[tid] =
        reinterpret_cast<const float4*>(g_pen)[m0 + tid];
    if (tid < 4) {
        int src = 4 * m0 + 1024 + tid;
        if (src >= V_SIZE) src -= V_SIZE;
        s_pen[1024 + tid] = g_pen[src];
    }

    // coverage loss in block (0,0), overlapped with the smem staging sync
    if (blockIdx.x == 0 && blockIdx.y == 0) {
        __shared__ float sg[8], sf[8];
        float f0 = g_firing[tid], f1 = g_firing[tid + 256];
        float g0 = 1.0f / (1.0f + __expf(-gate_logits[tid]));
        float g1 = 1.0f / (1.0f + __expf(-gate_logits[tid + 256]));
        float f = f0 + f1;
        float gf = g0 * f0 + g1 * f1;
        #pragma unroll
        for (int off = 16; off > 0; off >>= 1) {
            gf += __shfl_down_sync(0xFFFFFFFF, gf, off);
            f  += __shfl_down_sync(0xFFFFFFFF, f,  off);
        }
        int warp = tid >> 5;
        if ((tid & 31) == 0) { sg[warp] = gf; sf[warp] = f; }
        __syncthreads();
        if (tid < 32) {
            float g2 = (tid < 8) ? sg[tid] : 0.0f;
            float f2 = (tid < 8) ? sf[tid] : 0.0f;
            #pragma unroll
            for (int off = 4; off > 0; off >>= 1) {
                g2 += __shfl_down_sync(0xFFFFFFFF, g2, off);
                f2 += __shfl_down_sync(0xFFFFFFFF, f2, off);
            }
            if (tid == 0) out_loss[0] = -g2 / fmaxf(f2, 1.0f);
        }
    } else {
        __syncthreads();
    }
    if (blockIdx.x == 0 && blockIdx.y == 0) __syncthreads();  // pair the path above
    __syncthreads();   // ensure s_pen staged for all (cheap; BAR floor ~7cyc)

    float4 p  = reinterpret_cast<const float4*>(s_pen)[tid];
    float4 pn = reinterpret_cast<const float4*>(s_pen)[tid + 1];
    float4 ps = make_float4(p.w, pn.x, pn.y, pn.z);

    int m = m0 + tid;
    int b0 = blockIdx.y * ROWS_PER_BLK;

    #pragma unroll
    for (int r = 0; r < ROWS_PER_BLK; r++) {
        int i = (b0 + r) * V4_SIZE + m;        // quad index, fits in int
        float4 l = __ldg(reinterpret_cast<const float4*>(logits) + i);
        float4 o;
        o.x = l.x - p.x; o.y = l.y - p.y; o.z = l.z - p.z; o.w = l.w - p.w;
        __stcs(reinterpret_cast<float4*>(modified) + i, o);
        if (i < pen_quads)
            __stcs(reinterpret_cast<float4*>(penalties + 3) + i, ps);
    }

    // head/tail scalars of penalties not covered by the aligned window
    if (blockIdx.x == 0 && blockIdx.y == 0 && tid == 0) {
        penalties[0] = g_pen[0];
        penalties[1] = g_pen[1];
        penalties[2] = g_pen[2];
        int BV = 64 * V_SIZE;
        penalties[BV - 1] = g_pen[V_SIZE - 1];
    }
}

extern "C" void kernel_launch(void* const* d_in, const int* in_sizes, int n_in,
                              void* d_out, int out_size) {
    const float* logits      = (const float*)d_in[0];
    const float* gate_logits = (const float*)d_in[1];
    const int*   rule_ids    = (const int*)d_in[2];
    const int*   token_ids   = (const int*)d_in[3];

    int BV = in_sizes[0];       // 8,192,000
    int E  = in_sizes[2];       // 1,000,000

    float* out       = (float*)d_out;
    float* modified  = out;                 // [BV]
    float* out_loss  = out + BV;            // [1]
    float* penalties = out + BV + 1;        // [BV], 4B-aligned

    // 1) zero scratch
    k_zero<<<125, 256>>>();

    // 2) scatter
    {
        int n_quads = E / 4;                        // 250,000
        int blocks = (n_quads + 1023) / 1024;       // 245
        k_scatter<<<blocks, 512>>>(gate_logits, rule_ids, token_ids, n_quads);
    }

    // 3) fused broadcast + penalties + loss
    {
        int pen_quads = (BV - 3) / 4;               // 2,047,999
        dim3 grid(V4_SIZE / 256, 64 / ROWS_PER_BLK);  // (125, 8)
        k_bcast<<<grid, 256>>>(logits, gate_logits, modified, penalties,
                               out_loss, pen_quads);
    }
}